// round 9
// baseline (speedup 1.0000x reference)
#include <cuda_runtime.h>

#define BS_      128
#define NF_      4
#define P_LO_    1024
#define P_HI_    16384
#define K_       9
#define NC_      36
#define THREADS_ 256
#define TILE_    256                  // hi points per CTA (PPT=1)
#define NTILES_  (P_HI_ / TILE_)      // 64

// Scratch for class grouping (allocation-free: __device__ globals).
__device__ int g_cls_count[NC_];
__device__ int g_cls_list[NC_][BS_];

// Deterministic prepass: one warp per class, ballot+popc prefix keeps batch order.
__global__ void build_lists_kernel(const int* __restrict__ cls_ids) {
    int w    = (blockIdx.x * blockDim.x + threadIdx.x) >> 5;   // class id
    int lane = threadIdx.x & 31;
    if (w >= NC_) return;
    int base = 0;
    #pragma unroll
    for (int chunk = 0; chunk < BS_ / 32; chunk++) {
        int i = chunk * 32 + lane;
        int v = cls_ids[i];
        unsigned m = __ballot_sync(0xffffffffu, v == w);
        if (v == w) {
            int rank = __popc(m & ((1u << lane) - 1));
            g_cls_list[w][base + rank] = i;
        }
        base += __popc(m);
    }
    if (lane == 0) g_cls_count[w] = base;
}

// One CTA per (class, feature, 256-pt hi tile), one hi point per thread.
// Samples processed in PAIRS: shared tile is transposed y_sh[lo][2] so one
// LDS.64 gather serves both samples. Each thread stages 4 lo-points x 2
// samples (8 floats) so the full P_LO=1024 tile is covered. Double-buffered,
// x prefetched, 1 sync per pair-group.
__global__ void __launch_bounds__(THREADS_, 5)
upsample_kernel(const float* __restrict__ x,
                const int*   __restrict__ nbr,
                const float* __restrict__ wmap,
                const float* __restrict__ blo,
                const float* __restrict__ bhi,
                float*       __restrict__ out)
{
    __shared__ float y_sh[2][P_LO_ * 2];   // [buf][lo*2 + s]  (16 KB)

    const int tile = blockIdx.x;
    const int f    = blockIdx.y;
    const int c    = blockIdx.z;
    const int n    = g_cls_count[c];
    if (n == 0) return;                       // block-uniform exit (before syncs)

    const int tid = threadIdx.x;
    const int p0  = tile * TILE_ + tid;       // this thread's hi point

    // ---- tile-constant state (once per CTA) ----
    const float* wp = wmap + (((size_t)c * NF_ + f) * P_HI_ + (size_t)p0) * K_;
    float wv[K_];
    #pragma unroll
    for (int k = 0; k < K_; k++) wv[k] = wp[k];

    const int* ip = nbr + (size_t)p0 * K_;
    int nb[K_];
    #pragma unroll
    for (int k = 0; k < K_; k++) nb[k] = ip[k] * 2;   // pre-scaled: float2 slot

    const float bh = bhi[((size_t)c * NF_ + f) * P_HI_ + p0];

    // bias_low for this thread's four staged lo points (4t .. 4t+3)
    const float4 bv = reinterpret_cast<const float4*>(
        blo + ((size_t)c * NF_ + f) * P_LO_)[tid];

    const float4* xb = reinterpret_cast<const float4*>(x);  // (b*4+f)*256 + t

    const int ng = (n + 1) >> 1;              // pair groups

    // prefetch group 0 (float4 = 4 lo points per sample; 256 thr * 4 = 1024)
    int b0 = g_cls_list[c][0];
    int b1 = g_cls_list[c][(1 < n) ? 1 : 0];
    float4 xa = xb[((size_t)b0 * NF_ + f) * (P_LO_ / 4) + tid];
    float4 xc = xb[((size_t)b1 * NF_ + f) * (P_LO_ / 4) + tid];

    for (int g = 0; g < ng; g++) {
        float* buf = y_sh[g & 1];
        // stage transposed: lo=4t..4t+3, each as (s0, s1) -> two STS.128
        float4* b4 = reinterpret_cast<float4*>(buf) + 2 * tid;
        b4[0] = make_float4(xa.x - bv.x, xc.x - bv.x, xa.y - bv.y, xc.y - bv.y);
        b4[1] = make_float4(xa.z - bv.z, xc.z - bv.z, xa.w - bv.w, xc.w - bv.w);

        const int  ob0    = b0, ob1 = b1;
        const bool second = (2 * g + 1) < n;

        if (g + 1 < ng) {                      // prefetch next pair's x
            int s2 = 2 * g + 2;
            int s3 = (s2 + 1 < n) ? s2 + 1 : s2;
            b0 = g_cls_list[c][s2];
            b1 = g_cls_list[c][s3];
            xa = xb[((size_t)b0 * NF_ + f) * (P_LO_ / 4) + tid];
            xc = xb[((size_t)b1 * NF_ + f) * (P_LO_ / 4) + tid];
        }

        __syncthreads();                       // staging visible; prev compute done

        float s0 = bh, s1 = bh;
        #pragma unroll
        for (int k = 0; k < K_; k++) {
            float2 v = *reinterpret_cast<const float2*>(buf + nb[k]);
            s0 = fmaf(wv[k], v.x, s0);
            s1 = fmaf(wv[k], v.y, s1);
        }

        out[((size_t)ob0 * NF_ + f) * P_HI_ + p0] = s0;
        if (second)
            out[((size_t)ob1 * NF_ + f) * P_HI_ + p0] = s1;
        // no trailing sync: next group writes the other buffer; sync(g+1)
        // orders this group's reads before group g+2's overwrite.
    }
}

extern "C" void kernel_launch(void* const* d_in, const int* in_sizes, int n_in,
                              void* d_out, int out_size) {
    const float* x    = (const float*)d_in[0];   // (BS, NF*P_LO) f32
    const int*   cls  = (const int*)  d_in[1];   // (BS,) i32
    const int*   nbr  = (const int*)  d_in[2];   // (P_HI, K) i32
    const float* wmap = (const float*)d_in[3];   // (NC, NF, P_HI, K) f32
    const float* blo  = (const float*)d_in[4];   // (NC, NF, P_LO) f32
    const float* bhi  = (const float*)d_in[5];   // (NC, NF, P_HI) f32
    float* out = (float*)d_out;                  // (BS, NF, P_HI) f32

    build_lists_kernel<<<2, 576>>>(cls);         // 36 warps, one per class
    dim3 grid(NTILES_, NF_, NC_);
    upsample_kernel<<<grid, THREADS_>>>(x, nbr, wmap, blo, bhi, out);
}